// round 5
// baseline (speedup 1.0000x reference)
#include <cuda_runtime.h>

// Problem constants
#define BB      2
#define SS      2048
#define DIMM    1024
#define NHEADS  16
#define HDIM    64
#define WIN     256
#define NTOK    (BB*SS)          // 4096

// Scratch for Q/K/V projections (device globals: allocation-free)
__device__ float g_q[NTOK * DIMM];
__device__ float g_k[NTOK * DIMM];
__device__ float g_v[NTOK * DIMM];

// ---------------- packed f32x2 helpers (Blackwell FFMA2 path) ----------------
typedef unsigned long long u64;

__device__ __forceinline__ u64 pack2(float lo, float hi) {
    u64 r; asm("mov.b64 %0, {%1, %2};" : "=l"(r) : "f"(lo), "f"(hi)); return r;
}
__device__ __forceinline__ float2 unpack2(u64 v) {
    float2 r; asm("mov.b64 {%0, %1}, %2;" : "=f"(r.x), "=f"(r.y) : "l"(v)); return r;
}
__device__ __forceinline__ u64 fma2(u64 a, u64 b, u64 c) {
    u64 d; asm("fma.rn.f32x2 %0, %1, %2, %3;" : "=l"(d) : "l"(a), "l"(b), "l"(c)); return d;
}
__device__ __forceinline__ u64 mul2(u64 a, u64 b) {
    u64 d; asm("mul.rn.f32x2 %0, %1, %2;" : "=l"(d) : "l"(a), "l"(b)); return d;
}
__device__ __forceinline__ u64 add2(u64 a, u64 b) {
    u64 d; asm("add.rn.f32x2 %0, %1, %2;" : "=l"(d) : "l"(a), "l"(b)); return d;
}
__device__ __forceinline__ float ex2_approx(float x) {
    float r; asm("ex2.approx.f32 %0, %1;" : "=f"(r) : "f"(x)); return r;
}
__device__ __forceinline__ float shfl_bfly1(float v) {
    float r; asm("shfl.sync.bfly.b32 %0, %1, 0x1, 0x1f, 0xffffffff;" : "=f"(r) : "f"(v));
    return r;
}

union F4U { float4 f; u64 u[2]; };

// ---------------- Kernel 1: fused QKV projection GEMM ----------------
#define BM  128
#define BN  128
#define BKK 16

__global__ void __launch_bounds__(256, 2) qkv_gemm(
    const float* __restrict__ X,
    const float* __restrict__ Wq, const float* __restrict__ bq,
    const float* __restrict__ Wk, const float* __restrict__ bk,
    const float* __restrict__ Wv, const float* __restrict__ bv)
{
    const float* W; const float* bias; float* C;
    if (blockIdx.z == 0)      { W = Wq; bias = bq; C = g_q; }
    else if (blockIdx.z == 1) { W = Wk; bias = bk; C = g_k; }
    else                      { W = Wv; bias = bv; C = g_v; }

    __shared__ float As[BKK][BM];
    __shared__ float Bs[BKK][BN];

    const int row0 = blockIdx.y * BM;
    const int col0 = blockIdx.x * BN;
    const int tid  = threadIdx.x;
    const int tx   = tid & 15;
    const int ty   = tid >> 4;
    const int lr   = tid >> 2;
    const int lc   = tid & 3;

    u64 acc[8][4];
    #pragma unroll
    for (int m = 0; m < 8; m++)
        #pragma unroll
        for (int n = 0; n < 4; n++) acc[m][n] = 0ull;

    const float* Xp = X + (row0 + lr) * DIMM + lc * 4;
    const float* Wp = W + (col0 + lr) * DIMM + lc * 4;

    float4 pa[2], pb[2];
    #pragma unroll
    for (int hh = 0; hh < 2; hh++) {
        pa[hh] = *(const float4*)(Xp + hh * 64 * DIMM);
        pb[hh] = *(const float4*)(Wp + hh * 64 * DIMM);
    }

    for (int k0 = 0; k0 < DIMM; k0 += BKK) {
        #pragma unroll
        for (int hh = 0; hh < 2; hh++) {
            const int r = lr + hh * 64;
            As[lc*4+0][r] = pa[hh].x; As[lc*4+1][r] = pa[hh].y;
            As[lc*4+2][r] = pa[hh].z; As[lc*4+3][r] = pa[hh].w;
            Bs[lc*4+0][r] = pb[hh].x; Bs[lc*4+1][r] = pb[hh].y;
            Bs[lc*4+2][r] = pb[hh].z; Bs[lc*4+3][r] = pb[hh].w;
        }
        __syncthreads();

        if (k0 + BKK < DIMM) {
            #pragma unroll
            for (int hh = 0; hh < 2; hh++) {
                pa[hh] = *(const float4*)(Xp + hh * 64 * DIMM + k0 + BKK);
                pb[hh] = *(const float4*)(Wp + hh * 64 * DIMM + k0 + BKK);
            }
        }

        #pragma unroll
        for (int kk = 0; kk < BKK; kk++) {
            float4 a0 = *(const float4*)&As[kk][ty * 8];
            float4 a1 = *(const float4*)&As[kk][ty * 8 + 4];
            F4U b0; b0.f = *(const float4*)&Bs[kk][tx * 8];
            F4U b1; b1.f = *(const float4*)&Bs[kk][tx * 8 + 4];
            u64 a2[8];
            a2[0] = pack2(a0.x, a0.x); a2[1] = pack2(a0.y, a0.y);
            a2[2] = pack2(a0.z, a0.z); a2[3] = pack2(a0.w, a0.w);
            a2[4] = pack2(a1.x, a1.x); a2[5] = pack2(a1.y, a1.y);
            a2[6] = pack2(a1.z, a1.z); a2[7] = pack2(a1.w, a1.w);
            u64 bb[4] = { b0.u[0], b0.u[1], b1.u[0], b1.u[1] };
            #pragma unroll
            for (int m = 0; m < 8; m++)
                #pragma unroll
                for (int n = 0; n < 4; n++)
                    acc[m][n] = fma2(a2[m], bb[n], acc[m][n]);
        }
        __syncthreads();
    }

    float bias8[8];
    #pragma unroll
    for (int n = 0; n < 8; n++) bias8[n] = bias[col0 + tx * 8 + n];

    #pragma unroll
    for (int m = 0; m < 8; m++) {
        float o[8];
        #pragma unroll
        for (int n = 0; n < 4; n++) {
            float2 v = unpack2(acc[m][n]);
            o[2*n]   = v.x + bias8[2*n];
            o[2*n+1] = v.y + bias8[2*n+1];
        }
        float* cp = C + (row0 + ty * 8 + m) * DIMM + col0 + tx * 8;
        *(float4*)(cp)     = make_float4(o[0], o[1], o[2], o[3]);
        *(float4*)(cp + 4) = make_float4(o[4], o[5], o[6], o[7]);
    }
}

// ---------------- Kernel 2: windowed flash attention ----------------
// 2 threads per query (lanes 2q, 2q+1 each own 32 head dims) -> half the
// register state (q2[16]+acc[16]) -> 4 blocks/SM target.
// 2-key interleaved inner loop; score finished via shfl.bfly(1) pair-reduce.
// Mask: key j visible to query i iff j < i + WIN.
#define KT  64
#define QPB 64   // queries per block (128 threads)

__global__ void __launch_bounds__(128, 4) attn_kernel(float* __restrict__ out)
{
    __shared__ float Ks[KT][HDIM];
    __shared__ float Vs[KT][HDIM];

    const int b  = blockIdx.z;
    const int hd = blockIdx.y;                                // head
    const int qt    = (int)gridDim.x - 1 - (int)blockIdx.x;   // heavy tiles first
    const int qbase = qt * QPB;
    const int t     = threadIdx.x;
    const int hf    = t & 1;          // which half of head_dim this thread owns
    const int i     = qbase + (t >> 1);                       // query index

    // q half-row pre-scaled by log2(e)/sqrt(D): 32 dims -> 16 u64
    u64 q2[16];
    {
        const float4* qp = (const float4*)(g_q + (b * SS + i) * DIMM + hd * HDIM + hf * 32);
        const float scale = 0.125f * 1.4426950408889634f;
        #pragma unroll
        for (int d4 = 0; d4 < 8; d4++) {
            float4 v = qp[d4];
            q2[2*d4]   = pack2(v.x * scale, v.y * scale);
            q2[2*d4+1] = pack2(v.z * scale, v.w * scale);
        }
    }

    u64 acc[16];
    #pragma unroll
    for (int d = 0; d < 16; d++) acc[d] = 0ull;
    float mrow = -3.0e38f, lrow = 0.0f;   // replicated in both pair threads

    const int jend = min(SS, qbase + (QPB - 1) + WIN);
    const float* Kbase = g_k + (b * SS) * DIMM + hd * HDIM;
    const float* Vbase = g_v + (b * SS) * DIMM + hd * HDIM;

    for (int j0 = 0; j0 < jend; j0 += KT) {
        const int nvalid = min(KT, jend - j0);
        __syncthreads();
        // 128 threads load K and V tiles: 1024 float4 slots each, 8 per thread per array
        #pragma unroll
        for (int u = 0; u < 8; u++) {
            int idx = t + u * 128;
            int row = idx >> 4;
            int c4  = idx & 15;
            if (row < nvalid) {
                ((float4*)Ks[row])[c4] = ((const float4*)(Kbase + (j0 + row) * DIMM))[c4];
                ((float4*)Vs[row])[c4] = ((const float4*)(Vbase + (j0 + row) * DIMM))[c4];
            }
        }
        __syncthreads();

        const int jlim = min(nvalid, i + WIN - j0);   // same for both pair threads
        int jj = 0;

        // ---- paired main loop: 2 keys per iteration ----
        for (; jj + 1 < jlim; jj += 2) {
            const float4* kr0 = (const float4*)&Ks[jj][hf * 32];
            const float4* kr1 = (const float4*)&Ks[jj + 1][hf * 32];
            u64 sa0 = 0ull, sb0 = 0ull, sa1 = 0ull, sb1 = 0ull;  // 4 indep chains
            #pragma unroll
            for (int d4 = 0; d4 < 8; d4 += 2) {
                F4U ka; ka.f = kr0[d4];
                F4U kb; kb.f = kr0[d4 + 1];
                F4U kc; kc.f = kr1[d4];
                F4U kd; kd.f = kr1[d4 + 1];
                sa0 = fma2(q2[2*d4],   ka.u[0], sa0);
                sb0 = fma2(q2[2*d4+1], ka.u[1], sb0);
                sa1 = fma2(q2[2*d4],   kc.u[0], sa1);
                sb1 = fma2(q2[2*d4+1], kc.u[1], sb1);
                sa0 = fma2(q2[2*d4+2], kb.u[0], sa0);
                sb0 = fma2(q2[2*d4+3], kb.u[1], sb0);
                sa1 = fma2(q2[2*d4+2], kd.u[0], sa1);
                sb1 = fma2(q2[2*d4+3], kd.u[1], sb1);
            }
            float2 sv0 = unpack2(add2(sa0, sb0));
            float2 sv1 = unpack2(add2(sa1, sb1));
            float s0 = sv0.x + sv0.y;
            float s1 = sv1.x + sv1.y;
            // pair-reduce across the two half-dim threads (both shfls overlap)
            s0 += shfl_bfly1(s0);
            s1 += shfl_bfly1(s1);

            // one rescale check per pair (identical decision in both threads)
            float mnew = fmaxf(mrow, fmaxf(s0, s1));
            if (mnew > mrow) {
                float corr = ex2_approx(mrow - mnew);
                mrow = mnew;
                lrow *= corr;
                u64 c2 = pack2(corr, corr);
                #pragma unroll
                for (int d = 0; d < 16; d++) acc[d] = mul2(acc[d], c2);
            }
            float p0 = ex2_approx(s0 - mrow);
            float p1 = ex2_approx(s1 - mrow);
            lrow += p0 + p1;
            u64 p02 = pack2(p0, p0);
            u64 p12 = pack2(p1, p1);

            const float4* vr0 = (const float4*)&Vs[jj][hf * 32];
            const float4* vr1 = (const float4*)&Vs[jj + 1][hf * 32];
            #pragma unroll
            for (int d4 = 0; d4 < 8; d4++) {
                F4U va; va.f = vr0[d4];
                F4U vb; vb.f = vr1[d4];
                acc[2*d4]   = fma2(p12, vb.u[0], fma2(p02, va.u[0], acc[2*d4]));
                acc[2*d4+1] = fma2(p12, vb.u[1], fma2(p02, va.u[1], acc[2*d4+1]));
            }
        }

        // ---- odd tail key ----
        if (jj < jlim) {
            const float4* kr = (const float4*)&Ks[jj][hf * 32];
            u64 sa = 0ull, sb = 0ull;
            #pragma unroll
            for (int d4 = 0; d4 < 8; d4 += 2) {
                F4U ka; ka.f = kr[d4];
                F4U kb; kb.f = kr[d4 + 1];
                sa = fma2(q2[2*d4],   ka.u[0], sa);
                sb = fma2(q2[2*d4+1], ka.u[1], sb);
                sa = fma2(q2[2*d4+2], kb.u[0], sa);
                sb = fma2(q2[2*d4+3], kb.u[1], sb);
            }
            float2 sv = unpack2(add2(sa, sb));
            float s = sv.x + sv.y;
            s += shfl_bfly1(s);
            if (s > mrow) {
                float corr = ex2_approx(mrow - s);
                mrow = s;
                lrow *= corr;
                u64 c2 = pack2(corr, corr);
                #pragma unroll
                for (int d = 0; d < 16; d++) acc[d] = mul2(acc[d], c2);
            }
            float p = ex2_approx(s - mrow);
            lrow += p;
            u64 p2 = pack2(p, p);
            const float4* vr = (const float4*)&Vs[jj][hf * 32];
            #pragma unroll
            for (int d4 = 0; d4 < 8; d4++) {
                F4U vu; vu.f = vr[d4];
                acc[2*d4]   = fma2(p2, vu.u[0], acc[2*d4]);
                acc[2*d4+1] = fma2(p2, vu.u[1], acc[2*d4+1]);
            }
        }
    }

    // output layout [B,S,H,D]: this thread writes its 32 dims
    const float inv = 1.0f / lrow;
    float* op = out + (b * SS + i) * DIMM + hd * HDIM + hf * 32;
    #pragma unroll
    for (int d4 = 0; d4 < 8; d4++) {
        float2 v0 = unpack2(acc[2*d4]);
        float2 v1 = unpack2(acc[2*d4+1]);
        ((float4*)op)[d4] = make_float4(v0.x * inv, v0.y * inv, v1.x * inv, v1.y * inv);
    }
}

// ---------------- launch ----------------
extern "C" void kernel_launch(void* const* d_in, const int* in_sizes, int n_in,
                              void* d_out, int out_size)
{
    const float* x  = (const float*)d_in[0];
    const float* Wq = (const float*)d_in[1];
    const float* bq = (const float*)d_in[2];
    const float* Wk = (const float*)d_in[3];
    const float* bk = (const float*)d_in[4];
    const float* Wv = (const float*)d_in[5];
    const float* bv = (const float*)d_in[6];
    float* out = (float*)d_out;

    dim3 ggrid(DIMM / BN, NTOK / BM, 3);   // 768 blocks
    qkv_gemm<<<ggrid, 256>>>(x, Wq, bq, Wk, bk, Wv, bv);

    dim3 agrid(SS / QPB, NHEADS, BB);      // 32 x 16 x 2 = 1024 blocks
    attn_kernel<<<agrid, 128>>>(out);
}

// round 6
// speedup vs baseline: 1.3702x; 1.3702x over previous
#include <cuda_runtime.h>

// Problem constants
#define BB      2
#define SS      2048
#define DIMM    1024
#define NHEADS  16
#define HDIM    64
#define WIN     256
#define NTOK    (BB*SS)          // 4096

// Scratch for Q/K/V projections (device globals: allocation-free)
__device__ float g_q[NTOK * DIMM];
__device__ float g_k[NTOK * DIMM];
__device__ float g_v[NTOK * DIMM];

// ---------------- packed f32x2 helpers (Blackwell FFMA2 path) ----------------
typedef unsigned long long u64;

__device__ __forceinline__ u64 pack2(float lo, float hi) {
    u64 r; asm("mov.b64 %0, {%1, %2};" : "=l"(r) : "f"(lo), "f"(hi)); return r;
}
__device__ __forceinline__ float2 unpack2(u64 v) {
    float2 r; asm("mov.b64 {%0, %1}, %2;" : "=f"(r.x), "=f"(r.y) : "l"(v)); return r;
}
__device__ __forceinline__ u64 fma2(u64 a, u64 b, u64 c) {
    u64 d; asm("fma.rn.f32x2 %0, %1, %2, %3;" : "=l"(d) : "l"(a), "l"(b), "l"(c)); return d;
}
__device__ __forceinline__ u64 mul2(u64 a, u64 b) {
    u64 d; asm("mul.rn.f32x2 %0, %1, %2;" : "=l"(d) : "l"(a), "l"(b)); return d;
}
__device__ __forceinline__ u64 add2(u64 a, u64 b) {
    u64 d; asm("add.rn.f32x2 %0, %1, %2;" : "=l"(d) : "l"(a), "l"(b)); return d;
}
__device__ __forceinline__ float ex2_approx(float x) {
    float r; asm("ex2.approx.f32 %0, %1;" : "=f"(r) : "f"(x)); return r;
}

union F4U { float4 f; u64 u[2]; };

// ---------------- Kernel 1: fused QKV projection GEMM ----------------
#define BM  128
#define BN  128
#define BKK 16

__global__ void __launch_bounds__(256, 2) qkv_gemm(
    const float* __restrict__ X,
    const float* __restrict__ Wq, const float* __restrict__ bq,
    const float* __restrict__ Wk, const float* __restrict__ bk,
    const float* __restrict__ Wv, const float* __restrict__ bv)
{
    const float* W; const float* bias; float* C;
    if (blockIdx.z == 0)      { W = Wq; bias = bq; C = g_q; }
    else if (blockIdx.z == 1) { W = Wk; bias = bk; C = g_k; }
    else                      { W = Wv; bias = bv; C = g_v; }

    __shared__ float As[BKK][BM];   // transposed: As[k][row]
    __shared__ float Bs[BKK][BN];   // transposed: Bs[k][col]

    const int row0 = blockIdx.y * BM;
    const int col0 = blockIdx.x * BN;
    const int tid  = threadIdx.x;
    const int tx   = tid & 15;
    const int ty   = tid >> 4;
    const int lr   = tid >> 2;
    const int lc   = tid & 3;

    u64 acc[8][4];
    #pragma unroll
    for (int m = 0; m < 8; m++)
        #pragma unroll
        for (int n = 0; n < 4; n++) acc[m][n] = 0ull;

    const float* Xp = X + (row0 + lr) * DIMM + lc * 4;
    const float* Wp = W + (col0 + lr) * DIMM + lc * 4;

    float4 pa[2], pb[2];
    #pragma unroll
    for (int hh = 0; hh < 2; hh++) {
        pa[hh] = *(const float4*)(Xp + hh * 64 * DIMM);
        pb[hh] = *(const float4*)(Wp + hh * 64 * DIMM);
    }

    for (int k0 = 0; k0 < DIMM; k0 += BKK) {
        #pragma unroll
        for (int hh = 0; hh < 2; hh++) {
            const int r = lr + hh * 64;
            As[lc*4+0][r] = pa[hh].x; As[lc*4+1][r] = pa[hh].y;
            As[lc*4+2][r] = pa[hh].z; As[lc*4+3][r] = pa[hh].w;
            Bs[lc*4+0][r] = pb[hh].x; Bs[lc*4+1][r] = pb[hh].y;
            Bs[lc*4+2][r] = pb[hh].z; Bs[lc*4+3][r] = pb[hh].w;
        }
        __syncthreads();

        if (k0 + BKK < DIMM) {
            #pragma unroll
            for (int hh = 0; hh < 2; hh++) {
                pa[hh] = *(const float4*)(Xp + hh * 64 * DIMM + k0 + BKK);
                pb[hh] = *(const float4*)(Wp + hh * 64 * DIMM + k0 + BKK);
            }
        }

        #pragma unroll
        for (int kk = 0; kk < BKK; kk++) {
            float4 a0 = *(const float4*)&As[kk][ty * 8];
            float4 a1 = *(const float4*)&As[kk][ty * 8 + 4];
            F4U b0; b0.f = *(const float4*)&Bs[kk][tx * 8];
            F4U b1; b1.f = *(const float4*)&Bs[kk][tx * 8 + 4];
            u64 a2[8];
            a2[0] = pack2(a0.x, a0.x); a2[1] = pack2(a0.y, a0.y);
            a2[2] = pack2(a0.z, a0.z); a2[3] = pack2(a0.w, a0.w);
            a2[4] = pack2(a1.x, a1.x); a2[5] = pack2(a1.y, a1.y);
            a2[6] = pack2(a1.z, a1.z); a2[7] = pack2(a1.w, a1.w);
            u64 bb[4] = { b0.u[0], b0.u[1], b1.u[0], b1.u[1] };
            #pragma unroll
            for (int m = 0; m < 8; m++)
                #pragma unroll
                for (int n = 0; n < 4; n++)
                    acc[m][n] = fma2(a2[m], bb[n], acc[m][n]);
        }
        __syncthreads();
    }

    float bias8[8];
    #pragma unroll
    for (int n = 0; n < 8; n++) bias8[n] = bias[col0 + tx * 8 + n];

    #pragma unroll
    for (int m = 0; m < 8; m++) {
        float o[8];
        #pragma unroll
        for (int n = 0; n < 4; n++) {
            float2 v = unpack2(acc[m][n]);
            o[2*n]   = v.x + bias8[2*n];
            o[2*n+1] = v.y + bias8[2*n+1];
        }
        float* cp = C + (row0 + ty * 8 + m) * DIMM + col0 + tx * 8;
        *(float4*)(cp)     = make_float4(o[0], o[1], o[2], o[3]);
        *(float4*)(cp + 4) = make_float4(o[4], o[5], o[6], o[7]);
    }
}

// ---------------- Kernel 2: windowed flash attention, 2-key interleaved ----------------
// Mask: key j visible to query i iff j < i + WIN.
// One query per thread (LDS-wavefront-optimal layout), 128 queries per block,
// K/V tiles of 64 in smem. Inner loop processes 2 keys per iteration:
// 4 independent score chains, one rescale check per pair, two overlapped ex2's.
#define KT 64

__global__ void __launch_bounds__(128) attn_kernel(float* __restrict__ out)
{
    __shared__ float Ks[KT][HDIM];
    __shared__ float Vs[KT][HDIM];

    const int b = blockIdx.z;
    const int h = blockIdx.y;
    const int qt    = (int)gridDim.x - 1 - (int)blockIdx.x;   // heavy tiles first
    const int qbase = qt * 128;
    const int t     = threadIdx.x;
    const int i     = qbase + t;

    // q row pre-scaled by log2(e)/sqrt(D)
    u64 q2[32];
    {
        const float4* qp = (const float4*)(g_q + (b * SS + i) * DIMM + h * HDIM);
        const float scale = 0.125f * 1.4426950408889634f;
        #pragma unroll
        for (int d4 = 0; d4 < 16; d4++) {
            float4 v = qp[d4];
            q2[2*d4]   = pack2(v.x * scale, v.y * scale);
            q2[2*d4+1] = pack2(v.z * scale, v.w * scale);
        }
    }

    u64 acc[32];
    #pragma unroll
    for (int d = 0; d < 32; d++) acc[d] = 0ull;
    float mrow = -3.0e38f, lrow = 0.0f;   // log2-domain running max / sum

    const int jend = min(SS, qbase + 127 + WIN);
    const float* Kbase = g_k + (b * SS) * DIMM + h * HDIM;
    const float* Vbase = g_v + (b * SS) * DIMM + h * HDIM;

    for (int j0 = 0; j0 < jend; j0 += KT) {
        const int nvalid = min(KT, jend - j0);
        __syncthreads();
        #pragma unroll
        for (int u = 0; u < 8; u++) {
            int idx = t + u * 128;
            int row = idx >> 4;
            int c4  = idx & 15;
            if (row < nvalid) {
                ((float4*)Ks[row])[c4] = ((const float4*)(Kbase + (j0 + row) * DIMM))[c4];
                ((float4*)Vs[row])[c4] = ((const float4*)(Vbase + (j0 + row) * DIMM))[c4];
            }
        }
        __syncthreads();

        const int jlim = min(nvalid, i + WIN - j0);   // per-thread window mask
        int jj = 0;

        // ---- paired main loop: 2 keys per iteration ----
        for (; jj + 1 < jlim; jj += 2) {
            const float4* kr0 = (const float4*)Ks[jj];
            const float4* kr1 = (const float4*)Ks[jj + 1];
            u64 sa0 = 0ull, sb0 = 0ull, sa1 = 0ull, sb1 = 0ull;  // 4 indep chains
            #pragma unroll
            for (int d4 = 0; d4 < 16; d4 += 2) {
                F4U ka; ka.f = kr0[d4];
                F4U kb; kb.f = kr0[d4 + 1];
                F4U kc; kc.f = kr1[d4];
                F4U kd; kd.f = kr1[d4 + 1];
                sa0 = fma2(q2[2*d4],   ka.u[0], sa0);
                sb0 = fma2(q2[2*d4+1], ka.u[1], sb0);
                sa1 = fma2(q2[2*d4],   kc.u[0], sa1);
                sb1 = fma2(q2[2*d4+1], kc.u[1], sb1);
                sa0 = fma2(q2[2*d4+2], kb.u[0], sa0);
                sb0 = fma2(q2[2*d4+3], kb.u[1], sb0);
                sa1 = fma2(q2[2*d4+2], kd.u[0], sa1);
                sb1 = fma2(q2[2*d4+3], kd.u[1], sb1);
            }
            float2 sv0 = unpack2(add2(sa0, sb0));
            float2 sv1 = unpack2(add2(sa1, sb1));
            float s0 = sv0.x + sv0.y;
            float s1 = sv1.x + sv1.y;

            // one rescale check per pair
            float mnew = fmaxf(mrow, fmaxf(s0, s1));
            if (mnew > mrow) {
                float corr = ex2_approx(mrow - mnew);
                mrow = mnew;
                lrow *= corr;
                u64 c2 = pack2(corr, corr);
                #pragma unroll
                for (int d = 0; d < 32; d++) acc[d] = mul2(acc[d], c2);
            }
            float p0 = ex2_approx(s0 - mrow);   // two MUFU ops overlap
            float p1 = ex2_approx(s1 - mrow);
            lrow += p0 + p1;
            u64 p02 = pack2(p0, p0);
            u64 p12 = pack2(p1, p1);

            const float4* vr0 = (const float4*)Vs[jj];
            const float4* vr1 = (const float4*)Vs[jj + 1];
            #pragma unroll
            for (int d4 = 0; d4 < 16; d4++) {
                F4U va; va.f = vr0[d4];
                F4U vb; vb.f = vr1[d4];
                acc[2*d4]   = fma2(p12, vb.u[0], fma2(p02, va.u[0], acc[2*d4]));
                acc[2*d4+1] = fma2(p12, vb.u[1], fma2(p02, va.u[1], acc[2*d4+1]));
            }
        }

        // ---- odd tail key ----
        if (jj < jlim) {
            const float4* kr = (const float4*)Ks[jj];
            u64 sa = 0ull, sb = 0ull;
            #pragma unroll
            for (int d4 = 0; d4 < 16; d4 += 2) {
                F4U ka; ka.f = kr[d4];
                F4U kb; kb.f = kr[d4 + 1];
                sa = fma2(q2[2*d4],   ka.u[0], sa);
                sb = fma2(q2[2*d4+1], ka.u[1], sb);
                sa = fma2(q2[2*d4+2], kb.u[0], sa);
                sb = fma2(q2[2*d4+3], kb.u[1], sb);
            }
            float2 sv = unpack2(add2(sa, sb));
            float s = sv.x + sv.y;
            if (s > mrow) {
                float corr = ex2_approx(mrow - s);
                mrow = s;
                lrow *= corr;
                u64 c2 = pack2(corr, corr);
                #pragma unroll
                for (int d = 0; d < 32; d++) acc[d] = mul2(acc[d], c2);
            }
            float p = ex2_approx(s - mrow);
            lrow += p;
            u64 p2 = pack2(p, p);
            const float4* vr = (const float4*)Vs[jj];
            #pragma unroll
            for (int d4 = 0; d4 < 16; d4++) {
                F4U vu; vu.f = vr[d4];
                acc[2*d4]   = fma2(p2, vu.u[0], acc[2*d4]);
                acc[2*d4+1] = fma2(p2, vu.u[1], acc[2*d4+1]);
            }
        }
    }

    // output layout [B,S,H,D]
    const float inv = 1.0f / lrow;
    float* op = out + (b * SS + i) * DIMM + h * HDIM;
    #pragma unroll
    for (int d4 = 0; d4 < 16; d4++) {
        float2 v0 = unpack2(acc[2*d4]);
        float2 v1 = unpack2(acc[2*d4+1]);
        ((float4*)op)[d4] = make_float4(v0.x * inv, v0.y * inv, v1.x * inv, v1.y * inv);
    }
}

// ---------------- launch ----------------
extern "C" void kernel_launch(void* const* d_in, const int* in_sizes, int n_in,
                              void* d_out, int out_size)
{
    const float* x  = (const float*)d_in[0];
    const float* Wq = (const float*)d_in[1];
    const float* bq = (const float*)d_in[2];
    const float* Wk = (const float*)d_in[3];
    const float* bk = (const float*)d_in[4];
    const float* Wv = (const float*)d_in[5];
    const float* bv = (const float*)d_in[6];
    float* out = (float*)d_out;

    dim3 ggrid(DIMM / BN, NTOK / BM, 3);   // 768 blocks
    qkv_gemm<<<ggrid, 256>>>(x, Wq, bq, Wk, bk, Wv, bv);

    dim3 agrid(SS / 128, NHEADS, BB);      // 512 blocks
    attn_kernel<<<agrid, 128>>>(out);
}

// round 7
// speedup vs baseline: 1.7602x; 1.2847x over previous
#include <cuda_runtime.h>
#include <cuda_bf16.h>

// Problem constants
#define BB      2
#define SS      2048
#define DIMM    1024
#define NHEADS  16
#define HDIM    64
#define WIN     256
#define NTOK    (BB*SS)          // 4096

// Scratch (device globals: allocation-free)
__device__ float g_q[NTOK * DIMM];
__device__ float g_k[NTOK * DIMM];
__device__ float g_v[NTOK * DIMM];
__device__ __nv_bfloat16 gx_hi[NTOK * DIMM];
__device__ __nv_bfloat16 gx_lo[NTOK * DIMM];
__device__ __nv_bfloat16 gw_hi[3 * DIMM * DIMM];
__device__ __nv_bfloat16 gw_lo[3 * DIMM * DIMM];

typedef unsigned long long u64;
typedef unsigned int u32;

// ---------------- packed f32x2 helpers (attention kernel) ----------------
__device__ __forceinline__ u64 pack2(float lo, float hi) {
    u64 r; asm("mov.b64 %0, {%1, %2};" : "=l"(r) : "f"(lo), "f"(hi)); return r;
}
__device__ __forceinline__ float2 unpack2(u64 v) {
    float2 r; asm("mov.b64 {%0, %1}, %2;" : "=f"(r.x), "=f"(r.y) : "l"(v)); return r;
}
__device__ __forceinline__ u64 fma2(u64 a, u64 b, u64 c) {
    u64 d; asm("fma.rn.f32x2 %0, %1, %2, %3;" : "=l"(d) : "l"(a), "l"(b), "l"(c)); return d;
}
__device__ __forceinline__ u64 mul2(u64 a, u64 b) {
    u64 d; asm("mul.rn.f32x2 %0, %1, %2;" : "=l"(d) : "l"(a), "l"(b)); return d;
}
__device__ __forceinline__ u64 add2(u64 a, u64 b) {
    u64 d; asm("add.rn.f32x2 %0, %1, %2;" : "=l"(d) : "l"(a), "l"(b)); return d;
}
__device__ __forceinline__ float ex2_approx(float x) {
    float r; asm("ex2.approx.f32 %0, %1;" : "=f"(r) : "f"(x)); return r;
}
union F4U { float4 f; u64 u[2]; };

// ---------------- tensor-core helpers ----------------
__device__ __forceinline__ void ldsm4(u32& r0, u32& r1, u32& r2, u32& r3, u32 addr) {
    asm volatile("ldmatrix.sync.aligned.m8n8.x4.shared.b16 {%0,%1,%2,%3}, [%4];"
                 : "=r"(r0), "=r"(r1), "=r"(r2), "=r"(r3) : "r"(addr));
}
__device__ __forceinline__ void mma_bf16(float* c, const u32* a, const u32* b) {
    asm volatile("mma.sync.aligned.m16n8k16.row.col.f32.bf16.bf16.f32 "
                 "{%0,%1,%2,%3}, {%4,%5,%6,%7}, {%8,%9}, {%0,%1,%2,%3};"
                 : "+f"(c[0]), "+f"(c[1]), "+f"(c[2]), "+f"(c[3])
                 : "r"(a[0]), "r"(a[1]), "r"(a[2]), "r"(a[3]), "r"(b[0]), "r"(b[1]));
}
__device__ __forceinline__ void cp16(u32 saddr, const void* gaddr) {
    asm volatile("cp.async.cg.shared.global [%0], [%1], 16;" :: "r"(saddr), "l"(gaddr));
}
__device__ __forceinline__ void cp_commit() { asm volatile("cp.async.commit_group;"); }
__device__ __forceinline__ void cp_wait1()  { asm volatile("cp.async.wait_group 1;"); }
__device__ __forceinline__ void cp_wait0()  { asm volatile("cp.async.wait_group 0;"); }
__device__ __forceinline__ u32 s2u(const void* p) { return (u32)__cvta_generic_to_shared(p); }

// ---------------- Kernel 0: fp32 -> bf16 hi/lo split ----------------
__global__ void split_bf16(const float* __restrict__ src,
                           __nv_bfloat16* __restrict__ hi,
                           __nv_bfloat16* __restrict__ lo, int n)
{
    int i = (blockIdx.x * blockDim.x + threadIdx.x) * 4;
    if (i >= n) return;
    float4 v = *(const float4*)(src + i);
    union { __nv_bfloat16 b[4]; uint2 u; } H, L;
    H.b[0] = __float2bfloat16(v.x); L.b[0] = __float2bfloat16(v.x - __bfloat162float(H.b[0]));
    H.b[1] = __float2bfloat16(v.y); L.b[1] = __float2bfloat16(v.y - __bfloat162float(H.b[1]));
    H.b[2] = __float2bfloat16(v.z); L.b[2] = __float2bfloat16(v.z - __bfloat162float(H.b[2]));
    H.b[3] = __float2bfloat16(v.w); L.b[3] = __float2bfloat16(v.w - __bfloat162float(H.b[3]));
    *(uint2*)(hi + i) = H.u;
    *(uint2*)(lo + i) = L.u;
}

// ---------------- Kernel 1: QKV GEMM on tensor cores (bf16 split) ----------------
// C[n,o] = sum_k X[n,k]*W[o,k] (NT). 128x128 tile, BK=16, 2-stage cp.async.
// 8 warps, warp tile 32x64. C = Xhi*Whi + Xhi*Wlo + Xlo*Whi, fp32 accum.
#define RS 24   // smem row stride in bf16 (48B): conflict-free ldmatrix, 16B-aligned

__global__ void __launch_bounds__(256) qkv_gemm_tc(
    const float* __restrict__ bq, const float* __restrict__ bk, const float* __restrict__ bv)
{
    // smem: [stage][matrix: Ah,Al,Bh,Bl][128*RS] = 2*4*6144B = 49152B (48KB)
    __shared__ __align__(16) __nv_bfloat16 sm[2][4][128 * RS];

    const int z = blockIdx.z;
    const __nv_bfloat16* Ahg = gx_hi;
    const __nv_bfloat16* Alg = gx_lo;
    const __nv_bfloat16* Bhg = gw_hi + z * DIMM * DIMM;
    const __nv_bfloat16* Blg = gw_lo + z * DIMM * DIMM;
    float* C = (z == 0) ? g_q : (z == 1) ? g_k : g_v;
    const float* bias = (z == 0) ? bq : (z == 1) ? bk : bv;

    const int row0 = blockIdx.y * 128;
    const int col0 = blockIdx.x * 128;
    const int tid  = threadIdx.x;
    const int wid  = tid >> 5;
    const int lane = tid & 31;
    const int wm   = (wid & 3) * 32;   // warp m-offset
    const int wn   = (wid >> 2) * 64;  // warp n-offset

    // cp.async mapping: per matrix, thread -> (row = tid/2, chunk = tid&1)
    const int ldrow = tid >> 1;
    const int ldc   = tid & 1;
    const __nv_bfloat16* gA = Ahg + (size_t)(row0 + ldrow) * DIMM + ldc * 8;
    const __nv_bfloat16* gAl= Alg + (size_t)(row0 + ldrow) * DIMM + ldc * 8;
    const __nv_bfloat16* gB = Bhg + (size_t)(col0 + ldrow) * DIMM + ldc * 8;
    const __nv_bfloat16* gBl= Blg + (size_t)(col0 + ldrow) * DIMM + ldc * 8;
    const u32 soff = ldrow * RS + ldc * 8;   // bf16 elements

    float acc[2][8][4];
    #pragma unroll
    for (int mi = 0; mi < 2; mi++)
        #pragma unroll
        for (int ni = 0; ni < 8; ni++)
            #pragma unroll
            for (int e = 0; e < 4; e++) acc[mi][ni][e] = 0.0f;

    // ldmatrix source offsets (bf16 elems)
    const int a_row = lane & 15, a_chk = lane >> 4;                    // A frags
    const int b_g = lane >> 3;
    const int b_row = (lane & 7) + ((b_g >> 1) << 3), b_chk = b_g & 1; // B frags

    // prologue: stage 0
    {
        cp16(s2u(&sm[0][0][soff]), gA);
        cp16(s2u(&sm[0][1][soff]), gAl);
        cp16(s2u(&sm[0][2][soff]), gB);
        cp16(s2u(&sm[0][3][soff]), gBl);
        cp_commit();
    }

    #pragma unroll 1
    for (int it = 0; it < DIMM / 16; it++) {
        const int s = it & 1;
        if (it + 1 < DIMM / 16) {
            const int kt = (it + 1) * 16;
            cp16(s2u(&sm[s^1][0][soff]), gA  + kt);
            cp16(s2u(&sm[s^1][1][soff]), gAl + kt);
            cp16(s2u(&sm[s^1][2][soff]), gB  + kt);
            cp16(s2u(&sm[s^1][3][soff]), gBl + kt);
            cp_commit();
            cp_wait1();
        } else {
            cp_wait0();
        }
        __syncthreads();

        // load fragments
        u32 ahi[2][4], alo[2][4], bhi[8][2], blo[8][2];
        #pragma unroll
        for (int mi = 0; mi < 2; mi++) {
            const int r = wm + mi * 16 + a_row;
            ldsm4(ahi[mi][0], ahi[mi][1], ahi[mi][2], ahi[mi][3], s2u(&sm[s][0][r * RS + a_chk * 8]));
            ldsm4(alo[mi][0], alo[mi][1], alo[mi][2], alo[mi][3], s2u(&sm[s][1][r * RS + a_chk * 8]));
        }
        #pragma unroll
        for (int p = 0; p < 4; p++) {
            const int r = wn + p * 16 + b_row;
            u32 r0, r1, r2, r3;
            ldsm4(r0, r1, r2, r3, s2u(&sm[s][2][r * RS + b_chk * 8]));
            bhi[2*p][0] = r0; bhi[2*p][1] = r1; bhi[2*p+1][0] = r2; bhi[2*p+1][1] = r3;
            ldsm4(r0, r1, r2, r3, s2u(&sm[s][3][r * RS + b_chk * 8]));
            blo[2*p][0] = r0; blo[2*p][1] = r1; blo[2*p+1][0] = r2; blo[2*p+1][1] = r3;
        }
        // 3-pass split mma: hi*hi + hi*lo + lo*hi
        #pragma unroll
        for (int mi = 0; mi < 2; mi++)
            #pragma unroll
            for (int ni = 0; ni < 8; ni++) {
                mma_bf16(acc[mi][ni], ahi[mi], bhi[ni]);
                mma_bf16(acc[mi][ni], ahi[mi], blo[ni]);
                mma_bf16(acc[mi][ni], alo[mi], bhi[ni]);
            }
        __syncthreads();
    }

    // epilogue: bias + store
    const int crow = lane >> 2;
    const int ccol = (lane & 3) * 2;
    #pragma unroll
    for (int ni = 0; ni < 8; ni++) {
        const int n = col0 + wn + ni * 8 + ccol;
        const float b0 = bias[n], b1 = bias[n + 1];
        #pragma unroll
        for (int mi = 0; mi < 2; mi++) {
            const int m = row0 + wm + mi * 16 + crow;
            float* cp0 = C + (size_t)m * DIMM + n;
            cp0[0] = acc[mi][ni][0] + b0;
            cp0[1] = acc[mi][ni][1] + b1;
            float* cp1 = C + (size_t)(m + 8) * DIMM + n;
            cp1[0] = acc[mi][ni][2] + b0;
            cp1[1] = acc[mi][ni][3] + b1;
        }
    }
}

// ---------------- Kernel 2: windowed flash attention, 2-key interleaved ----------------
// (unchanged from best-known config)
#define KT 64

__global__ void __launch_bounds__(128) attn_kernel(float* __restrict__ out)
{
    __shared__ float Ks[KT][HDIM];
    __shared__ float Vs[KT][HDIM];

    const int b = blockIdx.z;
    const int h = blockIdx.y;
    const int qt    = (int)gridDim.x - 1 - (int)blockIdx.x;   // heavy tiles first
    const int qbase = qt * 128;
    const int t     = threadIdx.x;
    const int i     = qbase + t;

    u64 q2[32];
    {
        const float4* qp = (const float4*)(g_q + (b * SS + i) * DIMM + h * HDIM);
        const float scale = 0.125f * 1.4426950408889634f;
        #pragma unroll
        for (int d4 = 0; d4 < 16; d4++) {
            float4 v = qp[d4];
            q2[2*d4]   = pack2(v.x * scale, v.y * scale);
            q2[2*d4+1] = pack2(v.z * scale, v.w * scale);
        }
    }

    u64 acc[32];
    #pragma unroll
    for (int d = 0; d < 32; d++) acc[d] = 0ull;
    float mrow = -3.0e38f, lrow = 0.0f;

    const int jend = min(SS, qbase + 127 + WIN);
    const float* Kbase = g_k + (b * SS) * DIMM + h * HDIM;
    const float* Vbase = g_v + (b * SS) * DIMM + h * HDIM;

    for (int j0 = 0; j0 < jend; j0 += KT) {
        const int nvalid = min(KT, jend - j0);
        __syncthreads();
        #pragma unroll
        for (int u = 0; u < 8; u++) {
            int idx = t + u * 128;
            int row = idx >> 4;
            int c4  = idx & 15;
            if (row < nvalid) {
                ((float4*)Ks[row])[c4] = ((const float4*)(Kbase + (j0 + row) * DIMM))[c4];
                ((float4*)Vs[row])[c4] = ((const float4*)(Vbase + (j0 + row) * DIMM))[c4];
            }
        }
        __syncthreads();

        const int jlim = min(nvalid, i + WIN - j0);
        int jj = 0;

        for (; jj + 1 < jlim; jj += 2) {
            const float4* kr0 = (const float4*)Ks[jj];
            const float4* kr1 = (const float4*)Ks[jj + 1];
            u64 sa0 = 0ull, sb0 = 0ull, sa1 = 0ull, sb1 = 0ull;
            #pragma unroll
            for (int d4 = 0; d4 < 16; d4 += 2) {
                F4U ka; ka.f = kr0[d4];
                F4U kb; kb.f = kr0[d4 + 1];
                F4U kc; kc.f = kr1[d4];
                F4U kd; kd.f = kr1[d4 + 1];
                sa0 = fma2(q2[2*d4],   ka.u[0], sa0);
                sb0 = fma2(q2[2*d4+1], ka.u[1], sb0);
                sa1 = fma2(q2[2*d4],   kc.u[0], sa1);
                sb1 = fma2(q2[2*d4+1], kc.u[1], sb1);
                sa0 = fma2(q2[2*d4+2], kb.u[0], sa0);
                sb0 = fma2(q2[2*d4+3], kb.u[1], sb0);
                sa1 = fma2(q2[2*d4+2], kd.u[0], sa1);
                sb1 = fma2(q2[2*d4+3], kd.u[1], sb1);
            }
            float2 sv0 = unpack2(add2(sa0, sb0));
            float2 sv1 = unpack2(add2(sa1, sb1));
            float s0 = sv0.x + sv0.y;
            float s1 = sv1.x + sv1.y;

            float mnew = fmaxf(mrow, fmaxf(s0, s1));
            if (mnew > mrow) {
                float corr = ex2_approx(mrow - mnew);
                mrow = mnew;
                lrow *= corr;
                u64 c2 = pack2(corr, corr);
                #pragma unroll
                for (int d = 0; d < 32; d++) acc[d] = mul2(acc[d], c2);
            }
            float p0 = ex2_approx(s0 - mrow);
            float p1 = ex2_approx(s1 - mrow);
            lrow += p0 + p1;
            u64 p02 = pack2(p0, p0);
            u64 p12 = pack2(p1, p1);

            const float4* vr0 = (const float4*)Vs[jj];
            const float4* vr1 = (const float4*)Vs[jj + 1];
            #pragma unroll
            for (int d4 = 0; d4 < 16; d4++) {
                F4U va; va.f = vr0[d4];
                F4U vb; vb.f = vr1[d4];
                acc[2*d4]   = fma2(p12, vb.u[0], fma2(p02, va.u[0], acc[2*d4]));
                acc[2*d4+1] = fma2(p12, vb.u[1], fma2(p02, va.u[1], acc[2*d4+1]));
            }
        }

        if (jj < jlim) {
            const float4* kr = (const float4*)Ks[jj];
            u64 sa = 0ull, sb = 0ull;
            #pragma unroll
            for (int d4 = 0; d4 < 16; d4 += 2) {
                F4U ka; ka.f = kr[d4];
                F4U kb; kb.f = kr[d4 + 1];
                sa = fma2(q2[2*d4],   ka.u[0], sa);
                sb = fma2(q2[2*d4+1], ka.u[1], sb);
                sa = fma2(q2[2*d4+2], kb.u[0], sa);
                sb = fma2(q2[2*d4+3], kb.u[1], sb);
            }
            float2 sv = unpack2(add2(sa, sb));
            float s = sv.x + sv.y;
            if (s > mrow) {
                float corr = ex2_approx(mrow - s);
                mrow = s;
                lrow *= corr;
                u64 c2 = pack2(corr, corr);
                #pragma unroll
                for (int d = 0; d < 32; d++) acc[d] = mul2(acc[d], c2);
            }
            float p = ex2_approx(s - mrow);
            lrow += p;
            u64 p2 = pack2(p, p);
            const float4* vr = (const float4*)Vs[jj];
            #pragma unroll
            for (int d4 = 0; d4 < 16; d4++) {
                F4U vu; vu.f = vr[d4];
                acc[2*d4]   = fma2(p2, vu.u[0], acc[2*d4]);
                acc[2*d4+1] = fma2(p2, vu.u[1], acc[2*d4+1]);
            }
        }
    }

    const float inv = 1.0f / lrow;
    float* op = out + (b * SS + i) * DIMM + h * HDIM;
    #pragma unroll
    for (int d4 = 0; d4 < 16; d4++) {
        float2 v0 = unpack2(acc[2*d4]);
        float2 v1 = unpack2(acc[2*d4+1]);
        ((float4*)op)[d4] = make_float4(v0.x * inv, v0.y * inv, v1.x * inv, v1.y * inv);
    }
}

// ---------------- launch ----------------
extern "C" void kernel_launch(void* const* d_in, const int* in_sizes, int n_in,
                              void* d_out, int out_size)
{
    const float* x  = (const float*)d_in[0];
    const float* Wq = (const float*)d_in[1];
    const float* bq = (const float*)d_in[2];
    const float* Wk = (const float*)d_in[3];
    const float* bk = (const float*)d_in[4];
    const float* Wv = (const float*)d_in[5];
    const float* bv = (const float*)d_in[6];
    float* out = (float*)d_out;

    __nv_bfloat16 *xhi, *xlo, *whi, *wlo;
    cudaGetSymbolAddress((void**)&xhi, gx_hi);
    cudaGetSymbolAddress((void**)&xlo, gx_lo);
    cudaGetSymbolAddress((void**)&whi, gw_hi);
    cudaGetSymbolAddress((void**)&wlo, gw_lo);

    // split fp32 -> bf16 hi/lo
    split_bf16<<<(NTOK * DIMM) / 1024, 256>>>(x, xhi, xlo, NTOK * DIMM);
    split_bf16<<<(DIMM * DIMM) / 1024, 256>>>(Wq, whi, wlo, DIMM * DIMM);
    split_bf16<<<(DIMM * DIMM) / 1024, 256>>>(Wk, whi + DIMM * DIMM, wlo + DIMM * DIMM, DIMM * DIMM);
    split_bf16<<<(DIMM * DIMM) / 1024, 256>>>(Wv, whi + 2 * DIMM * DIMM, wlo + 2 * DIMM * DIMM, DIMM * DIMM);

    // tensor-core QKV projection
    dim3 ggrid(DIMM / 128, NTOK / 128, 3);   // 8 x 32 x 3 = 768 blocks
    qkv_gemm_tc<<<ggrid, 256>>>(bq, bk, bv);

    // attention
    dim3 agrid(SS / 128, NHEADS, BB);        // 512 blocks
    attn_kernel<<<agrid, 128>>>(out);
}

// round 9
// speedup vs baseline: 3.9528x; 2.2456x over previous
#include <cuda_runtime.h>
#include <cuda_bf16.h>

// Problem constants
#define BB      2
#define SS      2048
#define DIMM    1024
#define NHEADS  16
#define HDIM    64
#define WIN     256
#define NTOK    (BB*SS)          // 4096

typedef unsigned long long u64;
typedef unsigned int u32;

// Scratch (device globals: allocation-free)
__device__ __nv_bfloat16 g_qhi[NTOK * DIMM];
__device__ __nv_bfloat16 g_qlo[NTOK * DIMM];
__device__ __nv_bfloat16 g_khi[NTOK * DIMM];
__device__ __nv_bfloat16 g_klo[NTOK * DIMM];
__device__ __nv_bfloat16 g_vhi[NTOK * DIMM];
__device__ __nv_bfloat16 g_vlo[NTOK * DIMM];
__device__ __nv_bfloat16 gx_hi[NTOK * DIMM];
__device__ __nv_bfloat16 gx_lo[NTOK * DIMM];
__device__ __nv_bfloat16 gw_hi[3 * DIMM * DIMM];
__device__ __nv_bfloat16 gw_lo[3 * DIMM * DIMM];

// ---------------- helpers ----------------
__device__ __forceinline__ float ex2_approx(float x) {
    float r; asm("ex2.approx.f32 %0, %1;" : "=f"(r) : "f"(x)); return r;
}
__device__ __forceinline__ void ldsm4(u32& r0, u32& r1, u32& r2, u32& r3, u32 addr) {
    asm volatile("ldmatrix.sync.aligned.m8n8.x4.shared.b16 {%0,%1,%2,%3}, [%4];"
                 : "=r"(r0), "=r"(r1), "=r"(r2), "=r"(r3) : "r"(addr));
}
__device__ __forceinline__ void ldsm4t(u32& r0, u32& r1, u32& r2, u32& r3, u32 addr) {
    asm volatile("ldmatrix.sync.aligned.m8n8.x4.trans.shared.b16 {%0,%1,%2,%3}, [%4];"
                 : "=r"(r0), "=r"(r1), "=r"(r2), "=r"(r3) : "r"(addr));
}
__device__ __forceinline__ void mma_bf16(float* c, const u32* a, const u32* b) {
    asm volatile("mma.sync.aligned.m16n8k16.row.col.f32.bf16.bf16.f32 "
                 "{%0,%1,%2,%3}, {%4,%5,%6,%7}, {%8,%9}, {%0,%1,%2,%3};"
                 : "+f"(c[0]), "+f"(c[1]), "+f"(c[2]), "+f"(c[3])
                 : "r"(a[0]), "r"(a[1]), "r"(a[2]), "r"(a[3]), "r"(b[0]), "r"(b[1]));
}
__device__ __forceinline__ void cp16(u32 saddr, const void* gaddr) {
    asm volatile("cp.async.cg.shared.global [%0], [%1], 16;" :: "r"(saddr), "l"(gaddr));
}
__device__ __forceinline__ void cp_commit() { asm volatile("cp.async.commit_group;"); }
__device__ __forceinline__ void cp_wait1()  { asm volatile("cp.async.wait_group 1;"); }
__device__ __forceinline__ void cp_wait0()  { asm volatile("cp.async.wait_group 0;"); }
__device__ __forceinline__ u32 s2u(const void* p) { return (u32)__cvta_generic_to_shared(p); }
__device__ __forceinline__ u32 bf16x2(float hi, float lo) {
    u32 d; asm("cvt.rn.bf16x2.f32 %0, %1, %2;" : "=r"(d) : "f"(hi), "f"(lo)); return d;
}
__device__ __forceinline__ float bfr(float x) {          // round-to-bf16, back to float
    return __bfloat162float(__float2bfloat16(x));
}

// ---------------- Kernel 0: fp32 -> bf16 hi/lo split ----------------
__global__ void split_bf16(const float* __restrict__ src,
                           __nv_bfloat16* __restrict__ hi,
                           __nv_bfloat16* __restrict__ lo, int n)
{
    int i = (blockIdx.x * blockDim.x + threadIdx.x) * 4;
    if (i >= n) return;
    float4 v = *(const float4*)(src + i);
    union { __nv_bfloat16 b[4]; uint2 u; } H, L;
    H.b[0] = __float2bfloat16(v.x); L.b[0] = __float2bfloat16(v.x - __bfloat162float(H.b[0]));
    H.b[1] = __float2bfloat16(v.y); L.b[1] = __float2bfloat16(v.y - __bfloat162float(H.b[1]));
    H.b[2] = __float2bfloat16(v.z); L.b[2] = __float2bfloat16(v.z - __bfloat162float(H.b[2]));
    H.b[3] = __float2bfloat16(v.w); L.b[3] = __float2bfloat16(v.w - __bfloat162float(H.b[3]));
    *(uint2*)(hi + i) = H.u;
    *(uint2*)(lo + i) = L.u;
}

// ---------------- Kernel 1: QKV GEMM on tensor cores (bf16 split) ----------------
// C = X @ W^T + b; epilogue writes bf16 hi/lo directly (q pre-scaled by log2e/8).
#define RS 24   // smem row stride in bf16 (48B)

__global__ void __launch_bounds__(256) qkv_gemm_tc(
    const float* __restrict__ bq, const float* __restrict__ bk, const float* __restrict__ bv)
{
    __shared__ __align__(16) __nv_bfloat16 sm[2][4][128 * RS];  // 48KB

    const int z = blockIdx.z;
    const __nv_bfloat16* Ahg = gx_hi;
    const __nv_bfloat16* Alg = gx_lo;
    const __nv_bfloat16* Bhg = gw_hi + z * DIMM * DIMM;
    const __nv_bfloat16* Blg = gw_lo + z * DIMM * DIMM;
    __nv_bfloat16* Chi = (z == 0) ? g_qhi : (z == 1) ? g_khi : g_vhi;
    __nv_bfloat16* Clo = (z == 0) ? g_qlo : (z == 1) ? g_klo : g_vlo;
    const float* bias = (z == 0) ? bq : (z == 1) ? bk : bv;
    const float scale = (z == 0) ? (0.125f * 1.4426950408889634f) : 1.0f;

    const int row0 = blockIdx.y * 128;
    const int col0 = blockIdx.x * 128;
    const int tid  = threadIdx.x;
    const int wid  = tid >> 5;
    const int lane = tid & 31;
    const int wm   = (wid & 3) * 32;
    const int wn   = (wid >> 2) * 64;

    const int ldrow = tid >> 1;
    const int ldc   = tid & 1;
    const __nv_bfloat16* gA = Ahg + (size_t)(row0 + ldrow) * DIMM + ldc * 8;
    const __nv_bfloat16* gAl= Alg + (size_t)(row0 + ldrow) * DIMM + ldc * 8;
    const __nv_bfloat16* gB = Bhg + (size_t)(col0 + ldrow) * DIMM + ldc * 8;
    const __nv_bfloat16* gBl= Blg + (size_t)(col0 + ldrow) * DIMM + ldc * 8;
    const u32 soff = ldrow * RS + ldc * 8;

    float acc[2][8][4];
    #pragma unroll
    for (int mi = 0; mi < 2; mi++)
        #pragma unroll
        for (int ni = 0; ni < 8; ni++)
            #pragma unroll
            for (int e = 0; e < 4; e++) acc[mi][ni][e] = 0.0f;

    const int a_row = lane & 15, a_chk = lane >> 4;
    const int b_g = lane >> 3;
    const int b_row = (lane & 7) + ((b_g >> 1) << 3), b_chk = b_g & 1;

    cp16(s2u(&sm[0][0][soff]), gA);
    cp16(s2u(&sm[0][1][soff]), gAl);
    cp16(s2u(&sm[0][2][soff]), gB);
    cp16(s2u(&sm[0][3][soff]), gBl);
    cp_commit();

    #pragma unroll 1
    for (int it = 0; it < DIMM / 16; it++) {
        const int s = it & 1;
        if (it + 1 < DIMM / 16) {
            const int kt = (it + 1) * 16;
            cp16(s2u(&sm[s^1][0][soff]), gA  + kt);
            cp16(s2u(&sm[s^1][1][soff]), gAl + kt);
            cp16(s2u(&sm[s^1][2][soff]), gB  + kt);
            cp16(s2u(&sm[s^1][3][soff]), gBl + kt);
            cp_commit();
            cp_wait1();
        } else {
            cp_wait0();
        }
        __syncthreads();

        u32 ahi[2][4], alo[2][4], bhi[8][2], blo[8][2];
        #pragma unroll
        for (int mi = 0; mi < 2; mi++) {
            const int r = wm + mi * 16 + a_row;
            ldsm4(ahi[mi][0], ahi[mi][1], ahi[mi][2], ahi[mi][3], s2u(&sm[s][0][r * RS + a_chk * 8]));
            ldsm4(alo[mi][0], alo[mi][1], alo[mi][2], alo[mi][3], s2u(&sm[s][1][r * RS + a_chk * 8]));
        }
        #pragma unroll
        for (int p = 0; p < 4; p++) {
            const int r = wn + p * 16 + b_row;
            u32 r0, r1, r2, r3;
            ldsm4(r0, r1, r2, r3, s2u(&sm[s][2][r * RS + b_chk * 8]));
            bhi[2*p][0] = r0; bhi[2*p][1] = r1; bhi[2*p+1][0] = r2; bhi[2*p+1][1] = r3;
            ldsm4(r0, r1, r2, r3, s2u(&sm[s][3][r * RS + b_chk * 8]));
            blo[2*p][0] = r0; blo[2*p][1] = r1; blo[2*p+1][0] = r2; blo[2*p+1][1] = r3;
        }
        #pragma unroll
        for (int mi = 0; mi < 2; mi++)
            #pragma unroll
            for (int ni = 0; ni < 8; ni++) {
                mma_bf16(acc[mi][ni], ahi[mi], bhi[ni]);
                mma_bf16(acc[mi][ni], ahi[mi], blo[ni]);
                mma_bf16(acc[mi][ni], alo[mi], bhi[ni]);
            }
        __syncthreads();
    }

    // epilogue: bias + scale + bf16 hi/lo split stores
    const int crow = lane >> 2;
    const int ccol = (lane & 3) * 2;
    #pragma unroll
    for (int ni = 0; ni < 8; ni++) {
        const int n = col0 + wn + ni * 8 + ccol;
        const float b0 = bias[n], b1 = bias[n + 1];
        #pragma unroll
        for (int mi = 0; mi < 2; mi++) {
            #pragma unroll
            for (int half = 0; half < 2; half++) {
                const int m = row0 + wm + mi * 16 + crow + half * 8;
                float o0 = (acc[mi][ni][2*half]   + b0) * scale;
                float o1 = (acc[mi][ni][2*half+1] + b1) * scale;
                float h0 = bfr(o0), h1 = bfr(o1);
                size_t off = ((size_t)m * DIMM + n) >> 1;   // u32 index
                ((u32*)Chi)[off] = bf16x2(h1, h0);
                ((u32*)Clo)[off] = bf16x2(o1 - h1, o0 - h0);
            }
        }
    }
}

// ---------------- Kernel 2: flash attention on tensor cores ----------------
// Block = (b, h, 64-query tile); 4 warps x 16 rows. Key tiles of 64.
// S = Qhi*Khi + Qhi*Klo + Qlo*Khi (q pre-scaled by log2e/8 in GEMM epilogue).
// O += Phi*Vhi + Phi*Vlo + Plo*Vhi, with P split after base-2 softmax.
#define LDK 72   // smem row stride in bf16 (144B) -> conflict-free ldmatrix

__global__ void __launch_bounds__(128) attn_mma(float* __restrict__ o_out)
{
    __shared__ __align__(16) __nv_bfloat16 skh[64 * LDK], skl[64 * LDK];
    __shared__ __align__(16) __nv_bfloat16 svh[64 * LDK], svl[64 * LDK];

    const int b  = blockIdx.z;
    const int h  = blockIdx.y;
    const int qt = (int)gridDim.x - 1 - (int)blockIdx.x;  // heavy tiles first
    const int q0 = qt * 64;
    const int tid = threadIdx.x;
    const int wid = tid >> 5;
    const int lane = tid & 31;
    const int wm = wid * 16;

    const int a_row = lane & 15, a_chk = lane >> 4;
    const int b_g = lane >> 3;
    const int b_row = (lane & 7) + ((b_g >> 1) << 3), b_chk = b_g & 1;

    // ---- load Q A-fragments (via smem staging in skh/skl) ----
    u32 qh[4][4], ql[4][4];
    {
        const __nv_bfloat16* gq  = g_qhi + (size_t)(b * SS + q0) * DIMM + h * HDIM;
        const __nv_bfloat16* gql = g_qlo + (size_t)(b * SS + q0) * DIMM + h * HDIM;
        #pragma unroll
        for (int u = 0; u < 4; u++) {
            int c = tid + u * 128;       // 512 chunks per array
            int row = c >> 3, cc = c & 7;
            cp16(s2u(&skh[row * LDK + cc * 8]), gq  + (size_t)row * DIMM + cc * 8);
            cp16(s2u(&skl[row * LDK + cc * 8]), gql + (size_t)row * DIMM + cc * 8);
        }
        cp_commit(); cp_wait0(); __syncthreads();
        #pragma unroll
        for (int kk = 0; kk < 4; kk++) {
            ldsm4(qh[kk][0], qh[kk][1], qh[kk][2], qh[kk][3],
                  s2u(&skh[(wm + a_row) * LDK + kk * 16 + a_chk * 8]));
            ldsm4(ql[kk][0], ql[kk][1], ql[kk][2], ql[kk][3],
                  s2u(&skl[(wm + a_row) * LDK + kk * 16 + a_chk * 8]));
        }
        __syncthreads();
    }

    float outf[8][4];
    #pragma unroll
    for (int ni = 0; ni < 8; ni++)
        #pragma unroll
        for (int e = 0; e < 4; e++) outf[ni][e] = 0.0f;
    float m0 = -1e30f, m1 = -1e30f, l0 = 0.0f, l1 = 0.0f;

    const int jend = min(SS, q0 + 63 + WIN);
    const __nv_bfloat16* Kh = g_khi + (size_t)(b * SS) * DIMM + h * HDIM;
    const __nv_bfloat16* Kl = g_klo + (size_t)(b * SS) * DIMM + h * HDIM;
    const __nv_bfloat16* Vh = g_vhi + (size_t)(b * SS) * DIMM + h * HDIM;
    const __nv_bfloat16* Vl = g_vlo + (size_t)(b * SS) * DIMM + h * HDIM;

    #pragma unroll 1
    for (int j0 = 0; j0 < jend; j0 += 64) {
        // ---- load K/V hi/lo tiles ----
        #pragma unroll
        for (int u = 0; u < 16; u++) {
            int c = tid + u * 128;               // 0..2047
            int arr = c >> 9, idx = c & 511;
            int row = idx >> 3, cc = idx & 7;
            size_t g = (size_t)(j0 + row) * DIMM + cc * 8;
            u32 d = (u32)(row * LDK + cc * 8);
            if      (arr == 0) cp16(s2u(&skh[d]), Kh + g);
            else if (arr == 1) cp16(s2u(&skl[d]), Kl + g);
            else if (arr == 2) cp16(s2u(&svh[d]), Vh + g);
            else               cp16(s2u(&svl[d]), Vl + g);
        }
        cp_commit(); cp_wait0(); __syncthreads();

        // ---- S = Q K^T (3-pass split) ----
        float s[8][4];
        #pragma unroll
        for (int ni = 0; ni < 8; ni++)
            #pragma unroll
            for (int e = 0; e < 4; e++) s[ni][e] = 0.0f;

        #pragma unroll
        for (int pj = 0; pj < 4; pj++) {
            #pragma unroll
            for (int kk = 0; kk < 4; kk++) {
                u32 h0, h1, h2, h3, lo0, lo1, lo2, lo3;
                ldsm4(h0, h1, h2, h3,   s2u(&skh[(pj * 16 + b_row) * LDK + kk * 16 + b_chk * 8]));
                ldsm4(lo0, lo1, lo2, lo3, s2u(&skl[(pj * 16 + b_row) * LDK + kk * 16 + b_chk * 8]));
                u32 Bh0[2] = {h0, h1}, Bh1[2] = {h2, h3};
                u32 Bl0[2] = {lo0, lo1}, Bl1[2] = {lo2, lo3};
                mma_bf16(s[2*pj],   qh[kk], Bh0);
                mma_bf16(s[2*pj],   qh[kk], Bl0);
                mma_bf16(s[2*pj],   ql[kk], Bh0);
                mma_bf16(s[2*pj+1], qh[kk], Bh1);
                mma_bf16(s[2*pj+1], qh[kk], Bl1);
                mma_bf16(s[2*pj+1], ql[kk], Bh1);
            }
        }

        // ---- diagonal mask tile: banned iff col >= row (j0 - q0 == WIN) ----
        if (j0 == q0 + WIN) {
            const int r0 = wm + (lane >> 2);
            const int c0 = (lane & 3) * 2;
            #pragma unroll
            for (int ni = 0; ni < 8; ni++) {
                int col = ni * 8 + c0;
                if (col     >= r0)     s[ni][0] = -1e30f;
                if (col + 1 >= r0)     s[ni][1] = -1e30f;
                if (col     >= r0 + 8) s[ni][2] = -1e30f;
                if (col + 1 >= r0 + 8) s[ni][3] = -1e30f;
            }
        }

        // ---- online softmax (base 2; scale folded into Q) ----
        float mx0 = -1e30f, mx1 = -1e30f;
        #pragma unroll
        for (int ni = 0; ni < 8; ni++) {
            mx0 = fmaxf(mx0, fmaxf(s[ni][0], s[ni][1]));
            mx1 = fmaxf(mx1, fmaxf(s[ni][2], s[ni][3]));
        }
        mx0 = fmaxf(mx0, __shfl_xor_sync(0xffffffffu, mx0, 1));
        mx0 = fmaxf(mx0, __shfl_xor_sync(0xffffffffu, mx0, 2));
        mx1 = fmaxf(mx1, __shfl_xor_sync(0xffffffffu, mx1, 1));
        mx1 = fmaxf(mx1, __shfl_xor_sync(0xffffffffu, mx1, 2));
        float nm0 = fmaxf(m0, mx0), nm1 = fmaxf(m1, mx1);
        float cr0 = ex2_approx(m0 - nm0), cr1 = ex2_approx(m1 - nm1);
        m0 = nm0; m1 = nm1; l0 *= cr0; l1 *= cr1;
        #pragma unroll
        for (int ni = 0; ni < 8; ni++) {
            outf[ni][0] *= cr0; outf[ni][1] *= cr0;
            outf[ni][2] *= cr1; outf[ni][3] *= cr1;
        }
        #pragma unroll
        for (int ni = 0; ni < 8; ni++) {
            s[ni][0] = ex2_approx(s[ni][0] - m0);
            s[ni][1] = ex2_approx(s[ni][1] - m0);
            s[ni][2] = ex2_approx(s[ni][2] - m1);
            s[ni][3] = ex2_approx(s[ni][3] - m1);
            l0 += s[ni][0] + s[ni][1];
            l1 += s[ni][2] + s[ni][3];
        }

        // ---- P V (3-pass split), V B-frags via ldmatrix.trans ----
        #pragma unroll
        for (int kk = 0; kk < 4; kk++) {
            // pack P A-fragment for this k-group (cols kk*16..kk*16+15)
            float p00 = s[2*kk][0],   p01 = s[2*kk][1],   p02 = s[2*kk][2],   p03 = s[2*kk][3];
            float p10 = s[2*kk+1][0], p11 = s[2*kk+1][1], p12 = s[2*kk+1][2], p13 = s[2*kk+1][3];
            float h00 = bfr(p00), h01 = bfr(p01), h02 = bfr(p02), h03 = bfr(p03);
            float h10 = bfr(p10), h11 = bfr(p11), h12 = bfr(p12), h13 = bfr(p13);
            u32 ph[4] = { bf16x2(h01, h00), bf16x2(h03, h02), bf16x2(h11, h10), bf16x2(h13, h12) };
            u32 pl[4] = { bf16x2(p01 - h01, p00 - h00), bf16x2(p03 - h03, p02 - h02),
                          bf16x2(p11 - h11, p10 - h10), bf16x2(p13 - h13, p12 - h12) };
            #pragma unroll
            for (int pd = 0; pd < 4; pd++) {
                u32 v0, v1, v2, v3, w0, w1, w2, w3;
                ldsm4t(v0, v1, v2, v3, s2u(&svh[(kk * 16 + a_row) * LDK + pd * 16 + a_chk * 8]));
                ldsm4t(w0, w1, w2, w3, s2u(&svl[(kk * 16 + a_row) * LDK + pd * 16 + a_chk * 8]));
                u32 Vh0[2] = {v0, v1}, Vh1[2] = {v2, v3};
                u32 Vl0[2] = {w0, w1}, Vl1[2] = {w2, w3};
                mma_bf16(outf[2*pd],   ph, Vh0);
                mma_bf16(outf[2*pd],   ph, Vl0);
                mma_bf16(outf[2*pd],   pl, Vh0);
                mma_bf16(outf[2*pd+1], ph, Vh1);
                mma_bf16(outf[2*pd+1], ph, Vl1);
                mma_bf16(outf[2*pd+1], pl, Vh1);
            }
        }
        __syncthreads();   // smem safe to overwrite next iteration
    }

    // ---- finalize: l reduce across quad, divide, store ----
    l0 += __shfl_xor_sync(0xffffffffu, l0, 1);
    l0 += __shfl_xor_sync(0xffffffffu, l0, 2);
    l1 += __shfl_xor_sync(0xffffffffu, l1, 1);
    l1 += __shfl_xor_sync(0xffffffffu, l1, 2);
    const float i0 = 1.0f / l0, i1 = 1.0f / l1;

    const int r0 = q0 + wm + (lane >> 2);
    const int c0 = (lane & 3) * 2;
    #pragma unroll
    for (int nd = 0; nd < 8; nd++) {
        const int d = nd * 8 + c0;
        float* p0 = o_out + (size_t)(b * SS + r0) * DIMM + h * HDIM + d;
        p0[0] = outf[nd][0] * i0;
        p0[1] = outf[nd][1] * i0;
        float* p1 = o_out + (size_t)(b * SS + r0 + 8) * DIMM + h * HDIM + d;
        p1[0] = outf[nd][2] * i1;
        p1[1] = outf[nd][3] * i1;
    }
}

// ---------------- launch ----------------
extern "C" void kernel_launch(void* const* d_in, const int* in_sizes, int n_in,
                              void* d_out, int out_size)
{
    const float* x  = (const float*)d_in[0];
    const float* Wq = (const float*)d_in[1];
    const float* bq = (const float*)d_in[2];
    const float* Wk = (const float*)d_in[3];
    const float* bk = (const float*)d_in[4];
    const float* Wv = (const float*)d_in[5];
    const float* bv = (const float*)d_in[6];
    float* out = (float*)d_out;

    __nv_bfloat16 *xhi, *xlo, *whi, *wlo;
    cudaGetSymbolAddress((void**)&xhi, gx_hi);
    cudaGetSymbolAddress((void**)&xlo, gx_lo);
    cudaGetSymbolAddress((void**)&whi, gw_hi);
    cudaGetSymbolAddress((void**)&wlo, gw_lo);

    split_bf16<<<(NTOK * DIMM) / 1024, 256>>>(x, xhi, xlo, NTOK * DIMM);
    split_bf16<<<(DIMM * DIMM) / 1024, 256>>>(Wq, whi, wlo, DIMM * DIMM);
    split_bf16<<<(DIMM * DIMM) / 1024, 256>>>(Wk, whi + DIMM * DIMM, wlo + DIMM * DIMM, DIMM * DIMM);
    split_bf16<<<(DIMM * DIMM) / 1024, 256>>>(Wv, whi + 2 * DIMM * DIMM, wlo + 2 * DIMM * DIMM, DIMM * DIMM);

    dim3 ggrid(DIMM / 128, NTOK / 128, 3);
    qkv_gemm_tc<<<ggrid, 256>>>(bq, bk, bv);

    dim3 agrid(SS / 64, NHEADS, BB);   // 32 x 16 x 2 = 1024 blocks
    attn_mma<<<agrid, 128>>>(out);
}